// round 15
// baseline (speedup 1.0000x reference)
#include <cuda_runtime.h>
#include <cuda_bf16.h>

#define Bsz 8
#define Sq  2048
#define Dd  256

__device__ unsigned short g_wh[Dd * Dd];
__device__ unsigned short g_wl[Dd * Dd];
__device__ unsigned short g_ph[(size_t)Bsz * (Sq + 1) * Dd];
__device__ unsigned short g_pl[(size_t)Bsz * (Sq + 1) * Dd];
__device__ unsigned short g_eh[(size_t)Bsz * Sq * Dd];
__device__ unsigned short g_el[(size_t)Bsz * Sq * Dd];
__device__ unsigned short g_eth[(size_t)Bsz * Dd * Sq];
__device__ unsigned short g_etl[(size_t)Bsz * Dd * Sq];
__device__ float g_pacc[768 * 64 * 256];
__device__ float g_pdn[768 * 64];

__device__ const signed char U_M[80] = {
    31,31,31,31, 30,30,30, 29,29,29, 28,28,28, 27,27,27, 26,26,26, 25,25,25,
    24,24,24, 23,23,23, 22,22, 21,21, 20,20, 19,19, 18,18, 17,17, 16,16, 15,15,
    14,13,12,11,10,9,8,7,
    30,22,14,6, 29,21,13,5, 28,20,12,4, 27,19,11,3, 26,18,10,2, 25,17,9,1, 24,16,8,0};
__device__ const signed char U_S[80] = {
    0,1,2,3, 0,1,2, 0,1,2, 0,1,2, 0,1,2, 0,1,2, 0,1,2,
    0,1,2, 0,1,2, 0,1, 0,1, 0,1, 0,1, 0,1, 0,1, 0,1, 0,1,
    0,0,0,0,0,0,0,0,
    3,2,1,0, 3,2,1,0, 3,2,1,0, 3,2,1,0, 3,2,1,0, 3,2,1,0, 3,2,1,0};

__device__ __forceinline__ unsigned pack_bf16(float a, float b) {
    __nv_bfloat162 t = __floats2bfloat162_rn(a, b);
    return *(unsigned*)&t;
}
__device__ __forceinline__ void mma16816(float* d, const unsigned* a, unsigned b0, unsigned b1) {
    asm volatile("mma.sync.aligned.m16n8k16.row.col.f32.bf16.bf16.f32 "
        "{%0,%1,%2,%3}, {%4,%5,%6,%7}, {%8,%9}, {%0,%1,%2,%3};"
        : "+f"(d[0]), "+f"(d[1]), "+f"(d[2]), "+f"(d[3])
        : "r"(a[0]), "r"(a[1]), "r"(a[2]), "r"(a[3]), "r"(b0), "r"(b1));
}
__device__ __forceinline__ void ldsm4(unsigned* r, unsigned addr) {
    asm volatile("ldmatrix.sync.aligned.m8n8.x4.shared.b16 {%0,%1,%2,%3}, [%4];"
        : "=r"(r[0]), "=r"(r[1]), "=r"(r[2]), "=r"(r[3]) : "r"(addr));
}
__device__ __forceinline__ unsigned smem_u32(const void* p) {
    unsigned a;
    asm("{ .reg .u64 t; cvta.to.shared.u64 t, %1; cvt.u32.u64 %0, t; }" : "=r"(a) : "l"(p));
    return a;
}
__device__ __forceinline__ void cpasync16(unsigned dst, const void* src) {
    asm volatile("cp.async.cg.shared.global [%0], [%1], 16;" :: "r"(dst), "l"(src));
}
#define CP_COMMIT() asm volatile("cp.async.commit_group;" ::: "memory")
#define CP_WAIT1()  asm volatile("cp.async.wait_group 1;" ::: "memory")
#define CP_WAIT0()  asm volatile("cp.async.wait_group 0;" ::: "memory")

// ---------------- kernel 1: W_eff fold -> bf16 hi/lo ----------------
__global__ void weff_kernel(const float* __restrict__ Wo) {
    int d = blockIdx.x, dp = threadIdx.x;
    float s = 0.f;
#pragma unroll
    for (int h = 0; h < 8; h++) s += Wo[(size_t)d * (Dd * 8) + h * Dd + dp];
    __nv_bfloat16 hb = __float2bfloat16(s);
    float hf = __bfloat162float(hb);
    __nv_bfloat16 lb = __float2bfloat16(s - hf);
    g_wh[d * Dd + dp] = *(unsigned short*)&hb;
    g_wl[d * Dd + dp] = *(unsigned short*)&lb;
}

// ---------------- kernel 2: fp32 -> bf16 hi/lo (sel: 0 = p, 1 = e) ----------------
__global__ void conv_kernel(const float* __restrict__ X, int sel) {
    unsigned short* Hi = sel ? g_eh : g_ph;
    unsigned short* Lo = sel ? g_el : g_pl;
    size_t i = (size_t)blockIdx.x * 256 + threadIdx.x;
    float4 v = ((const float4*)X)[i];
    float hx = __bfloat162float(__float2bfloat16(v.x));
    float hy = __bfloat162float(__float2bfloat16(v.y));
    float hz = __bfloat162float(__float2bfloat16(v.z));
    float hw = __bfloat162float(__float2bfloat16(v.w));
    ((uint2*)Hi)[i] = make_uint2(pack_bf16(hx, hy), pack_bf16(hz, hw));
    ((uint2*)Lo)[i] = make_uint2(pack_bf16(v.x - hx, v.y - hy), pack_bf16(v.z - hz, v.w - hw));
}

// ---------------- kernel 3: e2t[b][c][s] via mma ----------------
#define EWH 0
#define EWL 8192
#define EEH 16384
#define EEL 49152
#define EW_TOTAL 81920

__global__ __launch_bounds__(512, 1) void e2t_mma_kernel() {
    extern __shared__ char smem[];
    unsigned sb = smem_u32(smem);
    int tid = threadIdx.x, w = tid >> 5, lane = tid & 31;
    int g = lane >> 2, t = lane & 3;
    int cq = w >> 2, sr = w & 3;
    int bx = blockIdx.x;
    int b = bx >> 3, s_in = (bx & 7) * 256;
    int c0 = blockIdx.y * 64;

    int l7 = lane & 7;
    int asel = lane >> 4, bsel = (lane >> 3) & 1;
    int aRow = cq * 16 + (lane & 15);

    float acc[32];
#pragma unroll
    for (int i = 0; i < 32; i++) acc[i] = 0.f;

    int wr = tid >> 3, wcp = tid & 7;
    int er = tid >> 1, ehf = tid & 1;
    const unsigned short* egsrc = ehf ? g_el : g_eh;
    unsigned edst = sb + (ehf ? EEL : EEH) + er * 128;

    for (int kit = 0; kit < 4; kit++) {
        int k0 = kit * 64;
        __syncthreads();
        {
            size_t gu = ((size_t)(c0 + wr) << 5) + (k0 >> 3) + wcp;
            unsigned pc = (unsigned)(wcp ^ (wr & 7));
            cpasync16(sb + EWH + wr * 128 + pc * 16, (const uint4*)g_wh + gu);
            cpasync16(sb + EWL + wr * 128 + pc * 16, (const uint4*)g_wl + gu);
        }
        {
            size_t gu = ((size_t)(b * Sq + s_in + er) << 5) + (k0 >> 3);
#pragma unroll
            for (int j = 0; j < 8; j++) {
                unsigned pc = (unsigned)(j ^ (er & 7));
                cpasync16(edst + pc * 16, (const uint4*)egsrc + gu + j);
            }
        }
        CP_COMMIT();
        CP_WAIT0();
        __syncthreads();

#pragma unroll
        for (int ks = 0; ks < 4; ks++) {
            unsigned pca = (unsigned)((2 * ks + asel) ^ l7);
            unsigned ah[4], al[4];
            ldsm4(ah, sb + EWH + aRow * 128 + pca * 16);
            ldsm4(al, sb + EWL + aRow * 128 + pca * 16);
#pragma unroll
            for (int jn = 0; jn < 4; jn++) {
                int brow = sr * 64 + jn * 16 + ((lane >> 4) << 3) + (lane & 7);
                unsigned pcb = (unsigned)((2 * ks + bsel) ^ l7);
                unsigned bh[4], bl[4];
                ldsm4(bh, sb + EEH + brow * 128 + pcb * 16);
                ldsm4(bl, sb + EEL + brow * 128 + pcb * 16);
                mma16816(acc + jn * 8,     ah, bh[0], bh[1]);
                mma16816(acc + jn * 8 + 4, ah, bh[2], bh[3]);
                mma16816(acc + jn * 8,     ah, bl[0], bl[1]);
                mma16816(acc + jn * 8 + 4, ah, bl[2], bl[3]);
                mma16816(acc + jn * 8,     al, bh[0], bh[1]);
                mma16816(acc + jn * 8 + 4, al, bh[2], bh[3]);
            }
        }
    }

    int lr0 = cq * 16 + g, lr1 = lr0 + 8;
#pragma unroll
    for (int jn = 0; jn < 4; jn++)
#pragma unroll
        for (int h = 0; h < 2; h++) {
            int col = sr * 64 + jn * 16 + h * 8 + 2 * t;
            int s = s_in + col;
            float a0 = acc[jn * 8 + h * 4 + 0], a1 = acc[jn * 8 + h * 4 + 1];
            float a2 = acc[jn * 8 + h * 4 + 2], a3 = acc[jn * 8 + h * 4 + 3];
            float h0 = __bfloat162float(__float2bfloat16(a0));
            float h1 = __bfloat162float(__float2bfloat16(a1));
            float h2 = __bfloat162float(__float2bfloat16(a2));
            float h3 = __bfloat162float(__float2bfloat16(a3));
            size_t i0 = (((size_t)(b * Dd + c0 + lr0)) * Sq + s) >> 1;
            size_t i1 = (((size_t)(b * Dd + c0 + lr1)) * Sq + s) >> 1;
            ((unsigned*)g_eth)[i0] = pack_bf16(h0, h1);
            ((unsigned*)g_etl)[i0] = pack_bf16(a0 - h0, a1 - h1);
            ((unsigned*)g_eth)[i1] = pack_bf16(h2, h3);
            ((unsigned*)g_etl)[i1] = pack_bf16(a2 - h2, a3 - h3);
        }
}

// ---------------- kernel 4: attention (256 thr, deep-ILP bf16 3-pass) ----------------
// smem map: Qh 32K | Ql 32K | Kh 32K | Kl 32K | Eh 36K | El 36K | Ph 9.25K | Pl 9.25K | Dn 512B
#define SQH 0
#define SQL 32768
#define SKH 65536
#define SKL 98304
#define SEH 131072
#define SEL 167936
#define SPH 204800
#define SPL 214272
#define SDN 223744
#define SM_TOTAL 224256
#define PSTR 37

__global__ __launch_bounds__(256, 1) void attn_mma_kernel(float* __restrict__ Out) {
    extern __shared__ char smem[];
    unsigned sb = smem_u32(smem);
    int tid = threadIdx.x, w = tid >> 5, lane = tid & 31;
    int g = lane >> 2, t = lane & 3;
    int quad = w >> 1;          // rows quad*16..+15
    int role = w & 1;           // MMA1 keys role*32..+31 ; MMA2 cols role*128..+127

    int u = blockIdx.x;
    int b = u & 7, idx = u >> 3;
    int m = U_M[idx], s = U_S[idx];
    int q0 = m * 64;
    int k0 = s * 512;
    int kend = (m + 1) * 64;
    if (kend > k0 + 512) kend = k0 + 512;
    bool finalTile = (m <= 7);

    // Q load (rows q0+1..q0+64) hi/lo, swizzled 512B rows
    {
        int r = tid >> 2;
        int cp = (tid & 3) * 8;
        const uint4* srcH = (const uint4*)g_ph + ((size_t)(b * (Sq + 1) + q0 + 1 + r)) * 32 + cp;
        const uint4* srcL = (const uint4*)g_pl + ((size_t)(b * (Sq + 1) + q0 + 1 + r)) * 32 + cp;
#pragma unroll
        for (int j = 0; j < 8; j++) {
            unsigned pc = (unsigned)((cp + j) ^ (r & 7));
            *(uint4*)(smem + SQH + r * 512 + pc * 16) = srcH[j];
            *(uint4*)(smem + SQL + r * 512 + pc * 16) = srcL[j];
        }
    }

    float acc[64];
#pragma unroll
    for (int i = 0; i < 64; i++) acc[i] = 0.f;
    float dsum0 = 0.f, dsum1 = 0.f;

    int l7 = lane & 7;
    int asel = lane >> 4;
    int bsel = (lane >> 3) & 1;
    int aRow = quad * 16 + (lane & 15);
    unsigned qbH = sb + SQH + aRow * 512;
    unsigned qbL = sb + SQL + aRow * 512;
    int krow0 = role * 32 + ((lane >> 4) << 3) + l7;
    unsigned kb0H = sb + SKH + krow0 * 512;
    unsigned kb0L = sb + SKL + krow0 * 512;
    unsigned kb1H = kb0H + 16 * 512;
    unsigned kb1L = kb0L + 16 * 512;
    int erow = role * 128 + ((lane >> 4) << 3) + l7;
    unsigned ebH = sb + SEH + erow * 144 + bsel * 16;
    unsigned ebL = sb + SEL + erow * 144 + bsel * 16;
    unsigned* P32h = (unsigned*)(smem + SPH);
    unsigned* P32l = (unsigned*)(smem + SPL);
    int prow0 = (quad * 16 + g) * PSTR;
    int prow1 = prow0 + 8 * PSTR;

    // cp.async assignments
    int krr = tid >> 2, kcp = (tid & 3) * 8;
    size_t kgu_base = ((size_t)(b * (Sq + 1) + krr)) * 32;
    size_t egu_base = (size_t)(b * 256 + tid) * 256;
    unsigned edH = sb + SEH + tid * 144;
    unsigned edL = sb + SEL + tid * 144;

    auto issueK = [&](int kb) {
        size_t gu = kgu_base + (size_t)kb * 32;
#pragma unroll
        for (int j = 0; j < 8; j++) {
            int ch = kcp + j;
            unsigned pc = (unsigned)(ch ^ (krr & 7));
            cpasync16(sb + SKH + krr * 512 + pc * 16, (const uint4*)g_ph + gu + ch);
            cpasync16(sb + SKL + krr * 512 + pc * 16, (const uint4*)g_pl + gu + ch);
        }
        CP_COMMIT();
    };
    auto issueE = [&](int kb) {
        size_t gu = egu_base + (kb >> 3);
#pragma unroll
        for (int j = 0; j < 8; j++) {
            cpasync16(edH + j * 16, (const uint4*)g_eth + gu + j);
            cpasync16(edL + j * 16, (const uint4*)g_etl + gu + j);
        }
        CP_COMMIT();
    };

    issueK(k0);
    issueE(k0);

    for (int kb = k0; kb < kend; kb += 64) {
        bool more = (kb + 64 < kend);
        CP_WAIT1();                 // K(kb) arrived
        __syncthreads();

        // ---- MMA1: S[16 rows x 32 keys], 4 accumulator banks, gap-3 chains
        float S[16];
#pragma unroll
        for (int i = 0; i < 16; i++) S[i] = 0.f;
#pragma unroll
        for (int ks = 0; ks < 16; ks++) {
            unsigned ach = (unsigned)(((2 * ks + asel) ^ l7) << 4);
            unsigned bch = (unsigned)(((2 * ks + bsel) ^ l7) << 4);
            unsigned ah[4], al[4], b0h[4], b1h[4], b0l[4], b1l[4];
            ldsm4(ah, qbH + ach);
            ldsm4(b0h, kb0H + bch);
            ldsm4(b1h, kb1H + bch);
            ldsm4(al, qbL + ach);
            ldsm4(b0l, kb0L + bch);
            ldsm4(b1l, kb1L + bch);
            mma16816(S,      ah, b0h[0], b0h[1]);
            mma16816(S + 4,  ah, b0h[2], b0h[3]);
            mma16816(S + 8,  ah, b1h[0], b1h[1]);
            mma16816(S + 12, ah, b1h[2], b1h[3]);
            mma16816(S,      ah, b0l[0], b0l[1]);
            mma16816(S + 4,  ah, b0l[2], b0l[3]);
            mma16816(S + 8,  ah, b1l[0], b1l[1]);
            mma16816(S + 12, ah, b1l[2], b1l[3]);
            mma16816(S,      al, b0h[0], b0h[1]);
            mma16816(S + 4,  al, b0h[2], b0h[3]);
            mma16816(S + 8,  al, b1h[0], b1h[1]);
            mma16816(S + 12, al, b1h[2], b1h[3]);
        }
        __syncthreads();            // done reading K
        if (more) issueK(kb + 64);

        // ---- exp epilogue -> P smem (4 key-tiles per warp)
        int r0 = q0 + quad * 16 + g, r1 = r0 + 8;
#pragma unroll
        for (int kt = 0; kt < 4; kt++) {
            int kc = kb + role * 32 + kt * 8 + 2 * t;
            float v0 = fminf(fmaxf(S[kt * 4 + 0] * 0.0625f, -10.f), 10.f);
            float v1 = fminf(fmaxf(S[kt * 4 + 1] * 0.0625f, -10.f), 10.f);
            float v2 = fminf(fmaxf(S[kt * 4 + 2] * 0.0625f, -10.f), 10.f);
            float v3 = fminf(fmaxf(S[kt * 4 + 3] * 0.0625f, -10.f), 10.f);
            float p0 = (kc     <= r0) ? __expf(v0) : 0.f;
            float p1 = (kc + 1 <= r0) ? __expf(v1) : 0.f;
            float p2 = (kc     <= r1) ? __expf(v2) : 0.f;
            float p3 = (kc + 1 <= r1) ? __expf(v3) : 0.f;
            dsum0 += p0 + p1;
            dsum1 += p2 + p3;
            float h0 = __bfloat162float(__float2bfloat16(p0));
            float h1 = __bfloat162float(__float2bfloat16(p1));
            float h2 = __bfloat162float(__float2bfloat16(p2));
            float h3 = __bfloat162float(__float2bfloat16(p3));
            int c32 = role * 16 + kt * 4 + t;
            P32h[prow0 + c32] = pack_bf16(h0, h1);
            P32h[prow1 + c32] = pack_bf16(h2, h3);
            P32l[prow0 + c32] = pack_bf16(p0 - h0, p1 - h1);
            P32l[prow1 + c32] = pack_bf16(p2 - h2, p3 - h3);
        }
        if (more) CP_WAIT1(); else CP_WAIT0();   // E(kb) arrived
        __syncthreads();            // E + P visible

        // ---- MMA2: acc[16 x 128 cols] += P[16x64] . E, paired jp for gap-3
#pragma unroll
        for (int ks = 0; ks < 4; ks++) {
            unsigned ph[4], pl[4];
            ph[0] = P32h[prow0 + ks * 8 + t];
            ph[1] = P32h[prow1 + ks * 8 + t];
            ph[2] = P32h[prow0 + ks * 8 + 4 + t];
            ph[3] = P32h[prow1 + ks * 8 + 4 + t];
            pl[0] = P32l[prow0 + ks * 8 + t];
            pl[1] = P32l[prow1 + ks * 8 + t];
            pl[2] = P32l[prow0 + ks * 8 + 4 + t];
            pl[3] = P32l[prow1 + ks * 8 + 4 + t];
#pragma unroll
            for (int jp2 = 0; jp2 < 4; jp2++) {
                unsigned eoA = (unsigned)((2 * jp2) * 2304 + ks * 32);
                unsigned eoB = eoA + 2304;
                unsigned ehA[4], elA[4], ehB[4], elB[4];
                ldsm4(ehA, ebH + eoA);
                ldsm4(ehB, ebH + eoB);
                ldsm4(elA, ebL + eoA);
                ldsm4(elB, ebL + eoB);
                float* aA = acc + (2 * jp2) * 8;
                float* aB = aA + 8;
                mma16816(aA,     ph, ehA[0], ehA[1]);
                mma16816(aA + 4, ph, ehA[2], ehA[3]);
                mma16816(aB,     ph, ehB[0], ehB[1]);
                mma16816(aB + 4, ph, ehB[2], ehB[3]);
                mma16816(aA,     pl, ehA[0], ehA[1]);
                mma16816(aA + 4, pl, ehA[2], ehA[3]);
                mma16816(aB,     pl, ehB[0], ehB[1]);
                mma16816(aB + 4, pl, ehB[2], ehB[3]);
                mma16816(aA,     ph, elA[0], elA[1]);
                mma16816(aA + 4, ph, elA[2], elA[3]);
                mma16816(aB,     ph, elB[0], elB[1]);
                mma16816(aB + 4, ph, elB[2], elB[3]);
            }
        }
        __syncthreads();            // done reading E + P
        if (more) issueE(kb + 64);
    }

    // denominators (per role-half)
    dsum0 += __shfl_xor_sync(0xFFFFFFFF, dsum0, 1);
    dsum0 += __shfl_xor_sync(0xFFFFFFFF, dsum0, 2);
    dsum1 += __shfl_xor_sync(0xFFFFFFFF, dsum1, 1);
    dsum1 += __shfl_xor_sync(0xFFFFFFFF, dsum1, 2);
    float* Dn = (float*)(smem + SDN);
    if (t == 0) {
        Dn[role * 64 + quad * 16 + g] = dsum0;
        Dn[role * 64 + quad * 16 + g + 8] = dsum1;
    }
    __syncthreads();

    int lr0 = quad * 16 + g, lr1 = lr0 + 8;
    float d0 = Dn[lr0] + Dn[64 + lr0];
    float d1 = Dn[lr1] + Dn[64 + lr1];

    if (finalTile) {
        int r0 = q0 + lr0, r1 = q0 + lr1;
        float inv0 = 1.f / ((float)(r0 + 1) * d0);
        float inv1 = 1.f / ((float)(r1 + 1) * d1);
        float* o0 = Out + ((size_t)(b * Sq + r0)) * 256;
        float* o1 = Out + ((size_t)(b * Sq + r1)) * 256;
#pragma unroll
        for (int jp = 0; jp < 8; jp++)
#pragma unroll
            for (int nt = 0; nt < 2; nt++) {
                int col = role * 128 + jp * 16 + nt * 8 + 2 * t;
                *(float2*)(o0 + col) = make_float2(acc[jp * 8 + nt * 4 + 0] * inv0,
                                                   acc[jp * 8 + nt * 4 + 1] * inv0);
                *(float2*)(o1 + col) = make_float2(acc[jp * 8 + nt * 4 + 2] * inv1,
                                                   acc[jp * 8 + nt * 4 + 3] * inv1);
            }
    } else {
        int slot = (b * 24 + (m - 8)) * 4 + s;
        float* pa = g_pacc + (size_t)slot * 16384;
        if (t == 0 && role == 0) {
            g_pdn[slot * 64 + lr0] = d0;
            g_pdn[slot * 64 + lr1] = d1;
        }
#pragma unroll
        for (int jp = 0; jp < 8; jp++)
#pragma unroll
            for (int nt = 0; nt < 2; nt++) {
                int col = role * 128 + jp * 16 + nt * 8 + 2 * t;
                *(float2*)(pa + lr0 * 256 + col) = make_float2(acc[jp * 8 + nt * 4 + 0],
                                                               acc[jp * 8 + nt * 4 + 1]);
                *(float2*)(pa + lr1 * 256 + col) = make_float2(acc[jp * 8 + nt * 4 + 2],
                                                               acc[jp * 8 + nt * 4 + 3]);
            }
    }
}

// ---------------- kernel 5: reduce split-k partials ----------------
__global__ void reduce_kernel(float* __restrict__ Out) {
    __shared__ float dns[64];
    int tile = blockIdx.x;
    int b = tile / 24, m = (tile % 24) + 8;
    int cnt = (m + 8) >> 3;
    int slot0 = (b * 24 + (m - 8)) * 4;
    int tid = threadIdx.x;
    if (tid < 64) {
        float d = 0.f;
        for (int s = 0; s < cnt; s++) d += g_pdn[(slot0 + s) * 64 + tid];
        dns[tid] = d;
    }
    __syncthreads();
    int q0 = m * 64;
    for (int i = tid; i < 16384; i += 256) {
        int r = i >> 8, c = i & 255;
        float a = 0.f;
        for (int s = 0; s < cnt; s++) a += g_pacc[(size_t)(slot0 + s) * 16384 + i];
        int q = q0 + r;
        Out[((size_t)(b * Sq + q)) * 256 + c] = a / ((float)(q + 1) * dns[r]);
    }
}

// ---------------------------------------------------------------------------
extern "C" void kernel_launch(void* const* d_in, const int* in_sizes, int n_in,
                              void* d_out, int out_size) {
    const float* e  = (const float*)d_in[0];
    const float* p  = (const float*)d_in[1];
    const float* Wo = (const float*)d_in[2];
    float* out = (float*)d_out;

    cudaFuncSetAttribute(attn_mma_kernel, cudaFuncAttributeMaxDynamicSharedMemorySize, SM_TOTAL);
    cudaFuncSetAttribute(e2t_mma_kernel, cudaFuncAttributeMaxDynamicSharedMemorySize, EW_TOTAL);

    weff_kernel<<<Dd, Dd>>>(Wo);
    conv_kernel<<<(Bsz * (Sq + 1) * Dd) / 1024, 256>>>(p, 0);
    conv_kernel<<<(Bsz * Sq * Dd) / 1024, 256>>>(e, 1);
    e2t_mma_kernel<<<dim3(64, 4), 512, EW_TOTAL>>>();
    attn_mma_kernel<<<640, 256, SM_TOTAL>>>(out);
    reduce_kernel<<<192, 256>>>(out);
}

// round 16
// speedup vs baseline: 1.3108x; 1.3108x over previous
#include <cuda_runtime.h>
#include <cuda_bf16.h>

#define Bsz 8
#define Sq  2048
#define Dd  256

__device__ unsigned short g_wh[Dd * Dd];
__device__ unsigned short g_wl[Dd * Dd];
__device__ unsigned short g_ph[(size_t)Bsz * (Sq + 1) * Dd];
__device__ unsigned short g_pl[(size_t)Bsz * (Sq + 1) * Dd];
__device__ unsigned short g_eh[(size_t)Bsz * Sq * Dd];
__device__ unsigned short g_el[(size_t)Bsz * Sq * Dd];
__device__ unsigned short g_eth[(size_t)Bsz * Dd * Sq];
__device__ unsigned short g_etl[(size_t)Bsz * Dd * Sq];
__device__ float g_pacc[768 * 64 * 256];   // 384 slots x (128x256)
__device__ float g_pdn[768 * 64];          // 384 slots x 128

// 40 units/batch for BM=128: (m, split) sorted by key-count desc
__device__ const signed char U_M[40] = {
    15,15,15,15, 14,14,14, 13,13,13, 12,12,12, 11,11,11, 10,10, 9,9, 8,8, 7,7,
    6,5,4,3,
    14,10,6,2, 13,9,5,1, 12,8,4,0};
__device__ const signed char U_S[40] = {
    0,1,2,3, 0,1,2, 0,1,2, 0,1,2, 0,1,2, 0,1, 0,1, 0,1, 0,1,
    0,0,0,0,
    3,2,1,0, 3,2,1,0, 3,2,1,0};

__device__ __forceinline__ unsigned pack_bf16(float a, float b) {
    __nv_bfloat162 t = __floats2bfloat162_rn(a, b);
    return *(unsigned*)&t;
}
__device__ __forceinline__ void mma16816(float* d, const unsigned* a, unsigned b0, unsigned b1) {
    asm volatile("mma.sync.aligned.m16n8k16.row.col.f32.bf16.bf16.f32 "
        "{%0,%1,%2,%3}, {%4,%5,%6,%7}, {%8,%9}, {%0,%1,%2,%3};"
        : "+f"(d[0]), "+f"(d[1]), "+f"(d[2]), "+f"(d[3])
        : "r"(a[0]), "r"(a[1]), "r"(a[2]), "r"(a[3]), "r"(b0), "r"(b1));
}
__device__ __forceinline__ void ldsm4(unsigned* r, unsigned addr) {
    asm volatile("ldmatrix.sync.aligned.m8n8.x4.shared.b16 {%0,%1,%2,%3}, [%4];"
        : "=r"(r[0]), "=r"(r[1]), "=r"(r[2]), "=r"(r[3]) : "r"(addr));
}
__device__ __forceinline__ unsigned smem_u32(const void* p) {
    unsigned a;
    asm("{ .reg .u64 t; cvta.to.shared.u64 t, %1; cvt.u32.u64 %0, t; }" : "=r"(a) : "l"(p));
    return a;
}
__device__ __forceinline__ void cpasync16(unsigned dst, const void* src) {
    asm volatile("cp.async.cg.shared.global [%0], [%1], 16;" :: "r"(dst), "l"(src));
}
#define CP_COMMIT() asm volatile("cp.async.commit_group;" ::: "memory")
#define CP_WAIT1()  asm volatile("cp.async.wait_group 1;" ::: "memory")
#define CP_WAIT0()  asm volatile("cp.async.wait_group 0;" ::: "memory")

// ---------------- kernel 1: W_eff fold -> bf16 hi/lo ----------------
__global__ void weff_kernel(const float* __restrict__ Wo) {
    int d = blockIdx.x, dp = threadIdx.x;
    float s = 0.f;
#pragma unroll
    for (int h = 0; h < 8; h++) s += Wo[(size_t)d * (Dd * 8) + h * Dd + dp];
    __nv_bfloat16 hb = __float2bfloat16(s);
    float hf = __bfloat162float(hb);
    __nv_bfloat16 lb = __float2bfloat16(s - hf);
    g_wh[d * Dd + dp] = *(unsigned short*)&hb;
    g_wl[d * Dd + dp] = *(unsigned short*)&lb;
}

// ---------------- kernel 2: fp32 -> bf16 hi/lo (sel: 0 = p, 1 = e) ----------------
__global__ void conv_kernel(const float* __restrict__ X, int sel) {
    unsigned short* Hi = sel ? g_eh : g_ph;
    unsigned short* Lo = sel ? g_el : g_pl;
    size_t i = (size_t)blockIdx.x * 256 + threadIdx.x;
    float4 v = ((const float4*)X)[i];
    float hx = __bfloat162float(__float2bfloat16(v.x));
    float hy = __bfloat162float(__float2bfloat16(v.y));
    float hz = __bfloat162float(__float2bfloat16(v.z));
    float hw = __bfloat162float(__float2bfloat16(v.w));
    ((uint2*)Hi)[i] = make_uint2(pack_bf16(hx, hy), pack_bf16(hz, hw));
    ((uint2*)Lo)[i] = make_uint2(pack_bf16(v.x - hx, v.y - hy), pack_bf16(v.z - hz, v.w - hw));
}

// ---------------- kernel 3: e2t[b][c][s] via mma ----------------
#define EWH 0
#define EWL 8192
#define EEH 16384
#define EEL 49152
#define EW_TOTAL 81920

__global__ __launch_bounds__(512, 1) void e2t_mma_kernel() {
    extern __shared__ char smem[];
    unsigned sb = smem_u32(smem);
    int tid = threadIdx.x, w = tid >> 5, lane = tid & 31;
    int g = lane >> 2, t = lane & 3;
    int cq = w >> 2, sr = w & 3;
    int bx = blockIdx.x;
    int b = bx >> 3, s_in = (bx & 7) * 256;
    int c0 = blockIdx.y * 64;

    int l7 = lane & 7;
    int asel = lane >> 4, bsel = (lane >> 3) & 1;
    int aRow = cq * 16 + (lane & 15);

    float acc[32];
#pragma unroll
    for (int i = 0; i < 32; i++) acc[i] = 0.f;

    int wr = tid >> 3, wcp = tid & 7;
    int er = tid >> 1, ehf = tid & 1;
    const unsigned short* egsrc = ehf ? g_el : g_eh;
    unsigned edst = sb + (ehf ? EEL : EEH) + er * 128;

    for (int kit = 0; kit < 4; kit++) {
        int k0 = kit * 64;
        __syncthreads();
        {
            size_t gu = ((size_t)(c0 + wr) << 5) + (k0 >> 3) + wcp;
            unsigned pc = (unsigned)(wcp ^ (wr & 7));
            cpasync16(sb + EWH + wr * 128 + pc * 16, (const uint4*)g_wh + gu);
            cpasync16(sb + EWL + wr * 128 + pc * 16, (const uint4*)g_wl + gu);
        }
        {
            size_t gu = ((size_t)(b * Sq + s_in + er) << 5) + (k0 >> 3);
#pragma unroll
            for (int j = 0; j < 8; j++) {
                unsigned pc = (unsigned)(j ^ (er & 7));
                cpasync16(edst + pc * 16, (const uint4*)egsrc + gu + j);
            }
        }
        CP_COMMIT();
        CP_WAIT0();
        __syncthreads();

#pragma unroll
        for (int ks = 0; ks < 4; ks++) {
            unsigned pca = (unsigned)((2 * ks + asel) ^ l7);
            unsigned ah[4], al[4];
            ldsm4(ah, sb + EWH + aRow * 128 + pca * 16);
            ldsm4(al, sb + EWL + aRow * 128 + pca * 16);
#pragma unroll
            for (int jn = 0; jn < 4; jn++) {
                int brow = sr * 64 + jn * 16 + ((lane >> 4) << 3) + (lane & 7);
                unsigned pcb = (unsigned)((2 * ks + bsel) ^ l7);
                unsigned bh[4], bl[4];
                ldsm4(bh, sb + EEH + brow * 128 + pcb * 16);
                ldsm4(bl, sb + EEL + brow * 128 + pcb * 16);
                mma16816(acc + jn * 8,     ah, bh[0], bh[1]);
                mma16816(acc + jn * 8 + 4, ah, bh[2], bh[3]);
                mma16816(acc + jn * 8,     ah, bl[0], bl[1]);
                mma16816(acc + jn * 8 + 4, ah, bl[2], bl[3]);
                mma16816(acc + jn * 8,     al, bh[0], bh[1]);
                mma16816(acc + jn * 8 + 4, al, bh[2], bh[3]);
            }
        }
    }

    int lr0 = cq * 16 + g, lr1 = lr0 + 8;
#pragma unroll
    for (int jn = 0; jn < 4; jn++)
#pragma unroll
        for (int h = 0; h < 2; h++) {
            int col = sr * 64 + jn * 16 + h * 8 + 2 * t;
            int s = s_in + col;
            float a0 = acc[jn * 8 + h * 4 + 0], a1 = acc[jn * 8 + h * 4 + 1];
            float a2 = acc[jn * 8 + h * 4 + 2], a3 = acc[jn * 8 + h * 4 + 3];
            float h0 = __bfloat162float(__float2bfloat16(a0));
            float h1 = __bfloat162float(__float2bfloat16(a1));
            float h2 = __bfloat162float(__float2bfloat16(a2));
            float h3 = __bfloat162float(__float2bfloat16(a3));
            size_t i0 = (((size_t)(b * Dd + c0 + lr0)) * Sq + s) >> 1;
            size_t i1 = (((size_t)(b * Dd + c0 + lr1)) * Sq + s) >> 1;
            ((unsigned*)g_eth)[i0] = pack_bf16(h0, h1);
            ((unsigned*)g_etl)[i0] = pack_bf16(a0 - h0, a1 - h1);
            ((unsigned*)g_eth)[i1] = pack_bf16(h2, h3);
            ((unsigned*)g_etl)[i1] = pack_bf16(a2 - h2, a3 - h3);
        }
}

// ---------------- kernel 4: attention (BM=128, BN=32, 512 thr) ----------------
// smem: Qh 64K | Ql 64K | Kh 16K | Kl 16K | Eh 20K | El 20K | Ph 10K | Pl 10K | Dn 1K
#define SQH 0
#define SQL 65536
#define SKH 131072
#define SKL 147456
#define SEH 163840
#define SEL 184320
#define SPH 204800
#define SPL 215040
#define SDN 225280
#define SM_TOTAL 226304
#define PSTR 20

__global__ __launch_bounds__(512, 1) void attn_mma_kernel(float* __restrict__ Out) {
    extern __shared__ char smem[];
    unsigned sb = smem_u32(smem);
    int tid = threadIdx.x, w = tid >> 5, lane = tid & 31;
    int g = lane >> 2, t = lane & 3;
    int oct = w >> 1;           // rows oct*16..+15 (of 128)
    int role = w & 1;           // MMA1 keys role*16..+15 ; MMA2 cols role*128..+127

    int u = blockIdx.x;
    int b = u & 7, idx = u >> 3;
    int m = U_M[idx], s = U_S[idx];
    int q0 = m * 128;
    int k0 = s * 512;
    int kend = (m + 1) * 128;
    if (kend > k0 + 512) kend = k0 + 512;
    bool finalTile = (m <= 3);

    // Q load (rows q0+1..q0+128) hi/lo, swizzled 512B rows
    {
        int r = tid >> 2;
        int cp = (tid & 3) * 8;
        const uint4* srcH = (const uint4*)g_ph + ((size_t)(b * (Sq + 1) + q0 + 1 + r)) * 32 + cp;
        const uint4* srcL = (const uint4*)g_pl + ((size_t)(b * (Sq + 1) + q0 + 1 + r)) * 32 + cp;
#pragma unroll
        for (int j = 0; j < 8; j++) {
            unsigned pc = (unsigned)((cp + j) ^ (r & 7));
            *(uint4*)(smem + SQH + r * 512 + pc * 16) = srcH[j];
            *(uint4*)(smem + SQL + r * 512 + pc * 16) = srcL[j];
        }
    }

    float acc[64];
#pragma unroll
    for (int i = 0; i < 64; i++) acc[i] = 0.f;
    float dsum0 = 0.f, dsum1 = 0.f;

    int l7 = lane & 7;
    int asel = lane >> 4;
    int bsel = (lane >> 3) & 1;
    int aRow = oct * 16 + (lane & 15);
    unsigned qbH = sb + SQH + aRow * 512;
    unsigned qbL = sb + SQL + aRow * 512;
    int krow = role * 16 + ((lane >> 4) << 3) + l7;
    unsigned kbH = sb + SKH + krow * 512;
    unsigned kbL = sb + SKL + krow * 512;
    int erow = role * 128 + ((lane >> 4) << 3) + l7;
    unsigned ebH = sb + SEH + erow * 80 + bsel * 16;
    unsigned ebL = sb + SEL + erow * 80 + bsel * 16;
    unsigned* P32h = (unsigned*)(smem + SPH);
    unsigned* P32l = (unsigned*)(smem + SPL);
    int prow0 = (oct * 16 + g) * PSTR;
    int prow1 = prow0 + 8 * PSTR;

    // cp.async assignments
    int krr = tid >> 4, kcp = (tid & 15) * 2;    // K: 32 rows, 2 uint4 each (h+l)
    size_t kgu_base = ((size_t)(b * (Sq + 1) + krr)) * 32 + kcp;
    int er = tid >> 1, ehf = tid & 1;            // E: 256 rows, hi or lo, 4x16B
    size_t egu_base = (size_t)(b * 256 + er) * 256;
    const unsigned short* egsrc = ehf ? g_etl : g_eth;
    unsigned edst = sb + (ehf ? SEL : SEH) + er * 80;

    auto issueK = [&](int kb) {
        size_t gu = kgu_base + (size_t)kb * 32;
        unsigned p0 = (unsigned)(kcp ^ (krr & 7));
        unsigned p1 = (unsigned)((kcp + 1) ^ (krr & 7));
        cpasync16(sb + SKH + krr * 512 + p0 * 16, (const uint4*)g_ph + gu);
        cpasync16(sb + SKH + krr * 512 + p1 * 16, (const uint4*)g_ph + gu + 1);
        cpasync16(sb + SKL + krr * 512 + p0 * 16, (const uint4*)g_pl + gu);
        cpasync16(sb + SKL + krr * 512 + p1 * 16, (const uint4*)g_pl + gu + 1);
        CP_COMMIT();
    };
    auto issueE = [&](int kb) {
        size_t gu = egu_base + (kb >> 3);
#pragma unroll
        for (int j = 0; j < 4; j++)
            cpasync16(edst + j * 16, (const uint4*)egsrc + gu + j);
        CP_COMMIT();
    };

    issueK(k0);
    issueE(k0);

    for (int kb = k0; kb < kend; kb += 32) {
        bool more = (kb + 32 < kend);
        CP_WAIT1();                 // K(kb) arrived
        __syncthreads();

        // ---- MMA1: S[16 rows x 16 keys] (role's key half)
        float S[8];
#pragma unroll
        for (int i = 0; i < 8; i++) S[i] = 0.f;
#pragma unroll
        for (int ks = 0; ks < 16; ks++) {
            unsigned ach = (unsigned)(((2 * ks + asel) ^ l7) << 4);
            unsigned bch = (unsigned)(((2 * ks + bsel) ^ l7) << 4);
            unsigned ah[4], al[4], bh[4], bl[4];
            ldsm4(ah, qbH + ach);
            ldsm4(bh, kbH + bch);
            ldsm4(al, qbL + ach);
            ldsm4(bl, kbL + bch);
            mma16816(S,     ah, bh[0], bh[1]);
            mma16816(S + 4, ah, bh[2], bh[3]);
            mma16816(S,     ah, bl[0], bl[1]);
            mma16816(S + 4, ah, bl[2], bl[3]);
            mma16816(S,     al, bh[0], bh[1]);
            mma16816(S + 4, al, bh[2], bh[3]);
        }
        __syncthreads();            // done reading K
        if (more) issueK(kb + 32);  // prefetch hides behind epilogue + MMA2

        // ---- exp epilogue -> P smem
        int r0 = q0 + oct * 16 + g, r1 = r0 + 8;
#pragma unroll
        for (int j = 0; j < 2; j++) {
            int kc = kb + role * 16 + j * 8 + 2 * t;
            float v0 = fminf(fmaxf(S[j * 4 + 0] * 0.0625f, -10.f), 10.f);
            float v1 = fminf(fmaxf(S[j * 4 + 1] * 0.0625f, -10.f), 10.f);
            float v2 = fminf(fmaxf(S[j * 4 + 2] * 0.0625f, -10.f), 10.f);
            float v3 = fminf(fmaxf(S[j * 4 + 3] * 0.0625f, -10.f), 10.f);
            float p0 = (kc     <= r0) ? __expf(v0) : 0.f;
            float p1 = (kc + 1 <= r0) ? __expf(v1) : 0.f;
            float p2 = (kc     <= r1) ? __expf(v2) : 0.f;
            float p3 = (kc + 1 <= r1) ? __expf(v3) : 0.f;
            dsum0 += p0 + p1;
            dsum1 += p2 + p3;
            float h0 = __bfloat162float(__float2bfloat16(p0));
            float h1 = __bfloat162float(__float2bfloat16(p1));
            float h2 = __bfloat162float(__float2bfloat16(p2));
            float h3 = __bfloat162float(__float2bfloat16(p3));
            int c32 = role * 8 + j * 4 + t;
            P32h[prow0 + c32] = pack_bf16(h0, h1);
            P32h[prow1 + c32] = pack_bf16(h2, h3);
            P32l[prow0 + c32] = pack_bf16(p0 - h0, p1 - h1);
            P32l[prow1 + c32] = pack_bf16(p2 - h2, p3 - h3);
        }
        if (more) CP_WAIT1(); else CP_WAIT0();   // E(kb) arrived
        __syncthreads();            // E + P visible

        // ---- MMA2: acc[16 x 128 cols] += P[16x32] . E (role's col half)
#pragma unroll
        for (int ks = 0; ks < 2; ks++) {
            unsigned ph[4], pl[4];
            ph[0] = P32h[prow0 + ks * 8 + t];
            ph[1] = P32h[prow1 + ks * 8 + t];
            ph[2] = P32h[prow0 + ks * 8 + 4 + t];
            ph[3] = P32h[prow1 + ks * 8 + 4 + t];
            pl[0] = P32l[prow0 + ks * 8 + t];
            pl[1] = P32l[prow1 + ks * 8 + t];
            pl[2] = P32l[prow0 + ks * 8 + 4 + t];
            pl[3] = P32l[prow1 + ks * 8 + 4 + t];
#pragma unroll
            for (int jn = 0; jn < 8; jn++) {
                unsigned eo = (unsigned)(jn * 1280 + ks * 32);
                unsigned eh[4], el[4];
                ldsm4(eh, ebH + eo);
                ldsm4(el, ebL + eo);
                mma16816(acc + jn * 8,     ph, eh[0], eh[1]);
                mma16816(acc + jn * 8 + 4, ph, eh[2], eh[3]);
                mma16816(acc + jn * 8,     pl, eh[0], eh[1]);
                mma16816(acc + jn * 8 + 4, pl, eh[2], eh[3]);
                mma16816(acc + jn * 8,     ph, el[0], el[1]);
                mma16816(acc + jn * 8 + 4, ph, el[2], el[3]);
            }
        }
        __syncthreads();            // done reading E + P
        if (more) issueE(kb + 32);  // prefetch hides behind next MMA1
    }

    // denominators (role halves of keys)
    dsum0 += __shfl_xor_sync(0xFFFFFFFF, dsum0, 1);
    dsum0 += __shfl_xor_sync(0xFFFFFFFF, dsum0, 2);
    dsum1 += __shfl_xor_sync(0xFFFFFFFF, dsum1, 1);
    dsum1 += __shfl_xor_sync(0xFFFFFFFF, dsum1, 2);
    float* Dn = (float*)(smem + SDN);
    if (t == 0) {
        Dn[role * 128 + oct * 16 + g] = dsum0;
        Dn[role * 128 + oct * 16 + g + 8] = dsum1;
    }
    __syncthreads();

    int lr0 = oct * 16 + g, lr1 = lr0 + 8;
    float d0 = Dn[lr0] + Dn[128 + lr0];
    float d1 = Dn[lr1] + Dn[128 + lr1];

    if (finalTile) {
        int r0 = q0 + lr0, r1 = q0 + lr1;
        float inv0 = 1.f / ((float)(r0 + 1) * d0);
        float inv1 = 1.f / ((float)(r1 + 1) * d1);
        float* o0 = Out + ((size_t)(b * Sq + r0)) * 256;
        float* o1 = Out + ((size_t)(b * Sq + r1)) * 256;
#pragma unroll
        for (int jn = 0; jn < 8; jn++)
#pragma unroll
            for (int nt = 0; nt < 2; nt++) {
                int col = role * 128 + jn * 16 + nt * 8 + 2 * t;
                *(float2*)(o0 + col) = make_float2(acc[jn * 8 + nt * 4 + 0] * inv0,
                                                   acc[jn * 8 + nt * 4 + 1] * inv0);
                *(float2*)(o1 + col) = make_float2(acc[jn * 8 + nt * 4 + 2] * inv1,
                                                   acc[jn * 8 + nt * 4 + 3] * inv1);
            }
    } else {
        int slot = (b * 12 + (m - 4)) * 4 + s;
        float* pa = g_pacc + (size_t)slot * 32768;
        if (t == 0 && role == 0) {
            g_pdn[slot * 128 + lr0] = d0;
            g_pdn[slot * 128 + lr1] = d1;
        }
#pragma unroll
        for (int jn = 0; jn < 8; jn++)
#pragma unroll
            for (int nt = 0; nt < 2; nt++) {
                int col = role * 128 + jn * 16 + nt * 8 + 2 * t;
                *(float2*)(pa + lr0 * 256 + col) = make_float2(acc[jn * 8 + nt * 4 + 0],
                                                               acc[jn * 8 + nt * 4 + 1]);
                *(float2*)(pa + lr1 * 256 + col) = make_float2(acc[jn * 8 + nt * 4 + 2],
                                                               acc[jn * 8 + nt * 4 + 3]);
            }
    }
}

// ---------------- kernel 5: reduce split-k partials (m >= 4) ----------------
__global__ void reduce_kernel(float* __restrict__ Out) {
    __shared__ float dns[128];
    int tile = blockIdx.x;                 // 0..95
    int b = tile / 12, m = (tile % 12) + 4;
    int cnt = (m + 4) >> 2;                // ceil((m+1)/4)
    int slot0 = (b * 12 + (m - 4)) * 4;
    int tid = threadIdx.x;
    if (tid < 128) {
        float d = 0.f;
        for (int s = 0; s < cnt; s++) d += g_pdn[(slot0 + s) * 128 + tid];
        dns[tid] = d;
    }
    __syncthreads();
    int q0 = m * 128;
    for (int i4 = tid; i4 < 8192; i4 += 256) {     // 8192 float4 = 128x256
        int r = i4 >> 6, c4 = i4 & 63;
        float4 a = make_float4(0.f, 0.f, 0.f, 0.f);
        for (int s = 0; s < cnt; s++) {
            float4 v = ((const float4*)g_pacc)[(size_t)(slot0 + s) * 8192 + i4];
            a.x += v.x; a.y += v.y; a.z += v.z; a.w += v.w;
        }
        int q = q0 + r;
        float inv = 1.f / ((float)(q + 1) * dns[r]);
        a.x *= inv; a.y *= inv; a.z *= inv; a.w *= inv;
        ((float4*)Out)[((size_t)(b * Sq + q) * 256 + c4 * 4) >> 2] = a;
    }
}

// ---------------------------------------------------------------------------
extern "C" void kernel_launch(void* const* d_in, const int* in_sizes, int n_in,
                              void* d_out, int out_size) {
    const float* e  = (const float*)d_in[0];
    const float* p  = (const float*)d_in[1];
    const float* Wo = (const float*)d_in[2];
    float* out = (float*)d_out;

    cudaFuncSetAttribute(attn_mma_kernel, cudaFuncAttributeMaxDynamicSharedMemorySize, SM_TOTAL);
    cudaFuncSetAttribute(e2t_mma_kernel, cudaFuncAttributeMaxDynamicSharedMemorySize, EW_TOTAL);

    weff_kernel<<<Dd, Dd>>>(Wo);
    conv_kernel<<<(Bsz * (Sq + 1) * Dd) / 1024, 256>>>(p, 0);
    conv_kernel<<<(Bsz * Sq * Dd) / 1024, 256>>>(e, 1);
    e2t_mma_kernel<<<dim3(64, 4), 512, EW_TOTAL>>>();
    attn_mma_kernel<<<320, 512, SM_TOTAL>>>(out);
    reduce_kernel<<<96, 256>>>(out);
}